// round 14
// baseline (speedup 1.0000x reference)
#include <cuda_runtime.h>
#include <cuda_bf16.h>
#include <cstdint>

#define NN 50000
#define EE 800000

// ---------------- device scratch (module-load allocated, allowed) ----------
__device__ int   g_count [2 * (NN + 1)];
__device__ int   g_rowptr[2 * (NN + 1)];
__device__ int   g_col   [2 * EE];
__device__ float g_z1 [(size_t)NN * 384];   // x @ [Wself_sum | Wn1[0] | Wn1[1]] + bias
__device__ float g_h1 [(size_t)NN * 128];   // relu(layer-1 output)
__device__ float g_z2 [(size_t)NN * 192];   // h1 @ [Wself2_sum | Wn2[0] | Wn2[1]] + bias
__device__ float g_h2 [(size_t)NN * 64];    // layer-2 output
__device__ float g_wc1[128 * 384];
__device__ float g_bc1[384];
__device__ float g_wc2[128 * 192];
__device__ float g_bc2[192];

// ---------------- packed f32x2 helpers (Blackwell FFMA2) -------------------
__device__ __forceinline__ unsigned long long pack2(float lo, float hi) {
    unsigned long long r;
    asm("mov.b64 %0, {%1, %2};" : "=l"(r) : "f"(lo), "f"(hi));
    return r;
}
__device__ __forceinline__ void unpack2(unsigned long long v, float& lo, float& hi) {
    asm("mov.b64 {%0, %1}, %2;" : "=f"(lo), "=f"(hi) : "l"(v));
}
__device__ __forceinline__ void ffma2(unsigned long long& d,
                                      unsigned long long a, unsigned long long b) {
    asm("fma.rn.f32x2 %0, %1, %2, %0;" : "+l"(d) : "l"(a), "l"(b));
}

// ---------------- CSR build -------------------------------------------------
__global__ void zero_counts_k() {
    int i = blockIdx.x * blockDim.x + threadIdx.x;
    if (i < 2 * (NN + 1)) g_count[i] = 0;
}

__global__ void count_k(const int* __restrict__ edges) {
    int idx = blockIdx.x * blockDim.x + threadIdx.x;
    if (idx >= 2 * EE) return;
    int r = idx / EE;
    int e = idx - r * EE;
    int dst = edges[r * 2 * EE + EE + e];
    atomicAdd(&g_count[r * (NN + 1) + dst], 1);
}

__device__ __forceinline__ int warp_incl_scan(int v, int lane) {
#pragma unroll
    for (int o = 1; o < 32; o <<= 1) {
        int t = __shfl_up_sync(0xffffffffu, v, o);
        if (lane >= o) v += t;
    }
    return v;
}

__global__ void scan_k() {
    int r = blockIdx.x;
    int* cnt = g_count  + r * (NN + 1);
    int* rp  = g_rowptr + r * (NN + 1);
    __shared__ int wsum[32];
    __shared__ int s_carry;
    __shared__ int s_total;
    int tid = threadIdx.x, lane = tid & 31, wid = tid >> 5;
    if (tid == 0) s_carry = 0;
    __syncthreads();
    for (int base = 0; base < NN; base += 1024) {
        int i = base + tid;
        int v = (i < NN) ? cnt[i] : 0;
        int incl = warp_incl_scan(v, lane);
        if (lane == 31) wsum[wid] = incl;
        __syncthreads();
        if (wid == 0) {
            int w = wsum[lane];
            int wi = warp_incl_scan(w, lane);
            wsum[lane] = wi - w;
            if (lane == 31) s_total = wi;
        }
        __syncthreads();
        int excl = s_carry + wsum[wid] + incl - v;
        if (i < NN) { rp[i] = excl; cnt[i] = excl; }
        __syncthreads();
        if (tid == 0) s_carry += s_total;
        __syncthreads();
    }
    if (threadIdx.x == 0) rp[NN] = s_carry;
}

__global__ void fill_k(const int* __restrict__ edges) {
    int idx = blockIdx.x * blockDim.x + threadIdx.x;
    if (idx >= 2 * EE) return;
    int r = idx / EE;
    int e = idx - r * EE;
    int src = edges[r * 2 * EE + e];
    int dst = edges[r * 2 * EE + EE + e];
    int p = atomicAdd(&g_count[r * (NN + 1) + dst], 1);
    g_col[r * EE + p] = src;
}

// ---------------- combined weight/bias builder (one launch) -----------------
// covers 128*384 (wc1) + 128*192 (wc2) + 384 (bc1) + 192 (bc2) elements
__global__ void buildW_k(const float* __restrict__ Ws1, const float* __restrict__ Wn1,
                         const float* __restrict__ b1,
                         const float* __restrict__ Ws2, const float* __restrict__ Wn2,
                         const float* __restrict__ b2) {
    int i = blockIdx.x * blockDim.x + threadIdx.x;
    if (i < 128 * 384) {
        int k = i / 384, c = i - k * 384;
        float v;
        if (c < 128) v = Ws1[k * 128 + c] + Ws1[128 * 128 + k * 128 + c];
        else {
            int r = (c - 128) >> 7, cc = (c - 128) & 127;
            v = Wn1[r * 128 * 128 + k * 128 + cc];
        }
        g_wc1[i] = v;
    } else if (i < 128 * 384 + 128 * 192) {
        int j = i - 128 * 384;
        int k = j / 192, c = j - k * 192;
        float v;
        if (c < 64) v = Ws2[k * 64 + c] + Ws2[128 * 64 + k * 64 + c];
        else {
            int r = (c - 64) >> 6, cc = (c - 64) & 63;
            v = Wn2[r * 128 * 64 + k * 64 + cc];
        }
        g_wc2[j] = v;
    } else if (i < 128 * 384 + 128 * 192 + 384) {
        int c = i - (128 * 384 + 128 * 192);
        g_bc1[c] = (c < 128) ? b1[c] + b1[128 + c] : 0.f;
    } else if (i < 128 * 384 + 128 * 192 + 384 + 192) {
        int c = i - (128 * 384 + 128 * 192 + 384);
        g_bc2[c] = (c < 64) ? b2[c] + b2[64 + c] : 0.f;
    }
}

// ---------------- SGEMM with packed FFMA2 -----------------------------------
// C[rows x FOUT] = A[rows x 128] @ W[128 x FOUT] + bias   (col-tiled by COLT)
// rowBase allows chunked launches for pipelining.
template <int FOUT, int COLT>
__global__ void __launch_bounds__(256) gemm2_k(const float* __restrict__ A,
                                               const float* __restrict__ W,
                                               const float* __restrict__ bias,
                                               float* __restrict__ C,
                                               int rowBase) {
    constexpr int TN = COLT / 16;   // 8 (COLT=128) or 6 (COLT=96)
    constexpr int KC = 32;
    __shared__ unsigned long long As2[KC][128];  // duplicated pairs (32 KB)
    __shared__ float Ws[KC][COLT];

    const int tid = threadIdx.x;
    const int ty = tid >> 4, tx = tid & 15;
    const int rowBlock = rowBase + blockIdx.x * 128;
    const int colBlock = blockIdx.y * COLT;

    unsigned long long acc[8][TN / 2];
#pragma unroll
    for (int i = 0; i < 8; i++)
#pragma unroll
        for (int j = 0; j < TN / 2; j++) acc[i][j] = 0ull;

    for (int kb = 0; kb < 128; kb += KC) {
#pragma unroll
        for (int it = 0; it < 4; it++) {
            int idx = tid + it * 256;      // 0..1023
            int row = idx >> 3;            // 0..127
            int kq  = idx & 7;             // k-quad 0..7
            float4 v = make_float4(0.f, 0.f, 0.f, 0.f);
            int grow = rowBlock + row;
            if (grow < NN)
                v = *(const float4*)(A + (size_t)grow * 128 + kb + kq * 4);
            As2[kq * 4 + 0][row] = pack2(v.x, v.x);
            As2[kq * 4 + 1][row] = pack2(v.y, v.y);
            As2[kq * 4 + 2][row] = pack2(v.z, v.z);
            As2[kq * 4 + 3][row] = pack2(v.w, v.w);
        }
#pragma unroll
        for (int idx = tid; idx < KC * COLT / 4; idx += 256) {
            int k  = idx / (COLT / 4);
            int c4 = idx - k * (COLT / 4);
            *(float4*)&Ws[k][c4 * 4] =
                *(const float4*)(W + (size_t)(kb + k) * FOUT + colBlock + c4 * 4);
        }
        __syncthreads();

#pragma unroll
        for (int k = 0; k < KC; k++) {
            unsigned long long a2[8];
            const ulonglong2* ap = (const ulonglong2*)&As2[k][ty * 8];
#pragma unroll
            for (int i = 0; i < 4; i++) {
                ulonglong2 t = ap[i];
                a2[2 * i] = t.x; a2[2 * i + 1] = t.y;
            }
            unsigned long long b2[TN / 2];
            if (TN == 8) {
                const ulonglong2* wp = (const ulonglong2*)&Ws[k][tx * TN];
#pragma unroll
                for (int j = 0; j < 2; j++) {
                    ulonglong2 t = wp[j];
                    b2[2 * j] = t.x; b2[2 * j + 1] = t.y;
                }
            } else {
                const unsigned long long* wp =
                    (const unsigned long long*)&Ws[k][tx * TN];
#pragma unroll
                for (int j = 0; j < TN / 2; j++) b2[j] = wp[j];
            }
#pragma unroll
            for (int i = 0; i < 8; i++)
#pragma unroll
                for (int j = 0; j < TN / 2; j++)
                    ffma2(acc[i][j], a2[i], b2[j]);
        }
        __syncthreads();
    }

#pragma unroll
    for (int i = 0; i < 8; i++) {
        int grow = rowBlock + ty * 8 + i;
        if (grow < NN) {
            float* cr = C + (size_t)grow * FOUT + colBlock + tx * TN;
            const float* bp = bias + colBlock + tx * TN;
#pragma unroll
            for (int j = 0; j < TN / 2; j++) {
                float lo, hi;
                unpack2(acc[i][j], lo, hi);
                float2 o = make_float2(lo + bp[2 * j], hi + bp[2 * j + 1]);
                *(float2*)(cr + 2 * j) = o;
            }
        }
    }
}

// ---------------- fused aggregation epilogues (unroll-4 for MLP) ------------
// layer 1: h1[n] = relu( Z1[n,0:128] + sum_r mean_{src in N_r(n)} Z1[src,128+128r:256+128r] )
// chunked by node range [nodeBase, nodeBase+nodeCount)
__global__ void agg1_k(int nodeBase, int nodeCount) {
    int gw   = (blockIdx.x * blockDim.x + threadIdx.x) >> 5;
    int lane = threadIdx.x & 31;
    if (gw >= nodeCount) return;
    int n = nodeBase + gw;
    float4 acc = ((const float4*)(g_z1 + (size_t)n * 384))[lane];
#pragma unroll
    for (int r = 0; r < 2; r++) {
        const int* rp  = g_rowptr + r * (NN + 1);
        const int* col = g_col    + r * EE;
        int s = rp[n], e = rp[n + 1];
        const float4* base = (const float4*)(g_z1 + 128 + r * 128) + lane;
        float4 sum = make_float4(0.f, 0.f, 0.f, 0.f);
        int j = s;
        for (; j + 3 < e; j += 4) {
            int s0 = col[j], s1 = col[j + 1], s2 = col[j + 2], s3 = col[j + 3];
            float4 v0 = __ldg(base + (size_t)s0 * 96);
            float4 v1 = __ldg(base + (size_t)s1 * 96);
            float4 v2 = __ldg(base + (size_t)s2 * 96);
            float4 v3 = __ldg(base + (size_t)s3 * 96);
            sum.x += v0.x + v1.x + v2.x + v3.x;
            sum.y += v0.y + v1.y + v2.y + v3.y;
            sum.z += v0.z + v1.z + v2.z + v3.z;
            sum.w += v0.w + v1.w + v2.w + v3.w;
        }
        for (; j < e; j++) {
            float4 v = __ldg(base + (size_t)col[j] * 96);
            sum.x += v.x; sum.y += v.y; sum.z += v.z; sum.w += v.w;
        }
        float inv = (e > s) ? 1.0f / (float)(e - s) : 0.0f;
        acc.x += sum.x * inv; acc.y += sum.y * inv;
        acc.z += sum.z * inv; acc.w += sum.w * inv;
    }
    acc.x = fmaxf(acc.x, 0.f); acc.y = fmaxf(acc.y, 0.f);
    acc.z = fmaxf(acc.z, 0.f); acc.w = fmaxf(acc.w, 0.f);
    ((float4*)(g_h1 + (size_t)n * 128))[lane] = acc;
}

// layer 2: h2[n] = Z2[n,0:64] + sum_r mean_{src in N_r(n)} Z2[src,64+64r:128+64r]
__global__ void agg2_k() {
    int gw   = (blockIdx.x * blockDim.x + threadIdx.x) >> 5;
    int lane = threadIdx.x & 31;
    if (gw >= NN) return;
    float2 acc = ((const float2*)(g_z2 + (size_t)gw * 192))[lane];
#pragma unroll
    for (int r = 0; r < 2; r++) {
        const int* rp  = g_rowptr + r * (NN + 1);
        const int* col = g_col    + r * EE;
        int s = rp[gw], e = rp[gw + 1];
        const float2* base = (const float2*)(g_z2 + 64 + r * 64) + lane;
        float2 sum = make_float2(0.f, 0.f);
        int j = s;
        for (; j + 3 < e; j += 4) {
            int s0 = col[j], s1 = col[j + 1], s2 = col[j + 2], s3 = col[j + 3];
            float2 v0 = __ldg(base + (size_t)s0 * 96);
            float2 v1 = __ldg(base + (size_t)s1 * 96);
            float2 v2 = __ldg(base + (size_t)s2 * 96);
            float2 v3 = __ldg(base + (size_t)s3 * 96);
            sum.x += v0.x + v1.x + v2.x + v3.x;
            sum.y += v0.y + v1.y + v2.y + v3.y;
        }
        for (; j < e; j++) {
            float2 v = __ldg(base + (size_t)col[j] * 96);
            sum.x += v.x; sum.y += v.y;
        }
        float inv = (e > s) ? 1.0f / (float)(e - s) : 0.0f;
        acc.x += sum.x * inv; acc.y += sum.y * inv;
    }
    ((float2*)(g_h2 + (size_t)gw * 64))[lane] = acc;
}

// ---------------- scoring: dot(h2[u], h2[v]) over pos + neg edges -----------
__global__ void score_k(const int* __restrict__ edges, const int* __restrict__ neg,
                        float* __restrict__ out) {
    int gid  = blockIdx.x * blockDim.x + threadIdx.x;
    int eidx = gid >> 3;
    int sub  = gid & 7;
    if (eidx >= 2 * EE) return;
    int u, v;
    if (eidx < EE) { u = edges[eidx];           v = edges[EE + eidx]; }
    else           { int e = eidx - EE; u = neg[e]; v = neg[EE + e]; }
    const float4* hu = (const float4*)(g_h2 + (size_t)u * 64);
    const float4* hv = (const float4*)(g_h2 + (size_t)v * 64);
    float4 a0 = hu[sub * 2], a1 = hu[sub * 2 + 1];
    float4 b0 = hv[sub * 2], b1 = hv[sub * 2 + 1];
    float s = a0.x * b0.x + a0.y * b0.y + a0.z * b0.z + a0.w * b0.w
            + a1.x * b1.x + a1.y * b1.y + a1.z * b1.z + a1.w * b1.w;
    s += __shfl_xor_sync(0xffffffffu, s, 1);
    s += __shfl_xor_sync(0xffffffffu, s, 2);
    s += __shfl_xor_sync(0xffffffffu, s, 4);
    if (sub == 0) out[eidx] = s;
}

// ---------------- launch -----------------------------------------------------
extern "C" void kernel_launch(void* const* d_in, const int* in_sizes, int n_in,
                              void* d_out, int out_size) {
    const float* x     = (const float*)d_in[0];
    const int*   edges = (const int*)  d_in[1];
    const int*   nege  = (const int*)  d_in[2];
    const float* Wn1   = (const float*)d_in[3];   // [2,128,128]
    const float* Ws1   = (const float*)d_in[4];
    const float* b1    = (const float*)d_in[5];
    const float* Wn2   = (const float*)d_in[6];   // [2,128,64]
    const float* Ws2   = (const float*)d_in[7];
    const float* b2    = (const float*)d_in[8];
    float* out = (float*)d_out;

    void *pz1_, *ph1_, *pz2_, *pwc1_, *pbc1_, *pwc2_, *pbc2_;
    cudaGetSymbolAddress(&pz1_,  g_z1);
    cudaGetSymbolAddress(&ph1_,  g_h1);
    cudaGetSymbolAddress(&pz2_,  g_z2);
    cudaGetSymbolAddress(&pwc1_, g_wc1);
    cudaGetSymbolAddress(&pbc1_, g_bc1);
    cudaGetSymbolAddress(&pwc2_, g_wc2);
    cudaGetSymbolAddress(&pbc2_, g_bc2);
    float* pz1  = (float*)pz1_;
    float* ph1  = (float*)ph1_;
    float* pz2  = (float*)pz2_;
    float* pwc1 = (float*)pwc1_;
    float* pbc1 = (float*)pbc1_;
    float* pwc2 = (float*)pwc2_;
    float* pbc2 = (float*)pbc2_;

    // Streams/events created lazily on the first (pre-capture) call; during
    // capture they become fork/join dependency edges in the graph.
    static cudaStream_t sB = nullptr;
    static cudaEvent_t evFork = nullptr, evCSR = nullptr, evG2done = nullptr;
    static cudaEvent_t evA[4] = {nullptr, nullptr, nullptr, nullptr};
    static cudaEvent_t evZ2   = nullptr;
    if (!sB) {
        cudaStreamCreateWithFlags(&sB, cudaStreamNonBlocking);
        cudaEventCreateWithFlags(&evFork,   cudaEventDisableTiming);
        cudaEventCreateWithFlags(&evCSR,    cudaEventDisableTiming);
        cudaEventCreateWithFlags(&evG2done, cudaEventDisableTiming);
        cudaEventCreateWithFlags(&evZ2,     cudaEventDisableTiming);
        for (int c = 0; c < 4; c++)
            cudaEventCreateWithFlags(&evA[c], cudaEventDisableTiming);
    }

    const int edgeBlocks     = (2 * EE + 255) / 256;       // 6250
    const int nodeWarpBlocks = (NN * 32 + 255) / 256;      // 6250
    const int gemmRowBlocks  = (NN + 127) / 128;           // 391

    // ---- fork: CSR build on side stream (independent of GEMM1) ----
    cudaEventRecord(evFork, 0);
    cudaStreamWaitEvent(sB, evFork, 0);
    zero_counts_k<<<(2 * (NN + 1) + 255) / 256, 256, 0, sB>>>();
    count_k<<<edgeBlocks, 256, 0, sB>>>(edges);
    scan_k<<<2, 1024, 0, sB>>>();
    fill_k<<<edgeBlocks, 256, 0, sB>>>(edges);
    cudaEventRecord(evCSR, sB);

    // ---- main stream: combined weights (one launch), then GEMM1 ----
    buildW_k<<<(128 * 384 + 128 * 192 + 384 + 192 + 255) / 256, 256>>>(
        Ws1, Wn1, b1, Ws2, Wn2, b2);
    gemm2_k<384, 128><<<dim3(gemmRowBlocks, 3), 256>>>(x, pwc1, pbc1, pz1, 0);

    // ---- chunked pipeline: agg1 (main, L2-bound) ↔ GEMM2 (side, fma-bound) ----
    // agg1 chunk c needs: full z1 (GEMM1) + CSR. GEMM2 chunk c needs h1 rows of chunk c.
    cudaStreamWaitEvent(0, evCSR, 0);
    const int chunkRB[4]   = {98, 98, 98, 97};              // row-blocks per chunk
    const int chunkBase[4] = {0, 98 * 128, 196 * 128, 294 * 128};
    for (int c = 0; c < 4; c++) {
        int nodeBase  = chunkBase[c];
        int nodeCount = (c < 3) ? chunkRB[c] * 128 : (NN - chunkBase[3]);
        agg1_k<<<(nodeCount * 32 + 255) / 256, 256>>>(nodeBase, nodeCount);
        cudaEventRecord(evA[c], 0);
        cudaStreamWaitEvent(sB, evA[c], 0);
        gemm2_k<192, 96><<<dim3(chunkRB[c], 2), 256, 0, sB>>>(ph1, pwc2, pbc2, pz2, nodeBase);
    }
    cudaEventRecord(evG2done, sB);

    // ---- join: agg2 needs all of z2 ----
    cudaStreamWaitEvent(0, evG2done, 0);
    agg2_k<<<nodeWarpBlocks, 256>>>();

    // ---- scoring: out[0:E]=pos, out[E:2E]=neg ----
    score_k<<<(2 * EE * 8 + 255) / 256, 256>>>(edges, nege, out);
}

// round 16
// speedup vs baseline: 1.0806x; 1.0806x over previous
#include <cuda_runtime.h>
#include <cuda_bf16.h>
#include <cstdint>

#define NN 50000
#define EE 800000

// ---------------- device scratch (module-load allocated, allowed) ----------
__device__ int   g_count [2 * (NN + 1)];
__device__ int   g_rowptr[2 * (NN + 1)];
__device__ int   g_col   [2 * EE];
__device__ float g_z1 [(size_t)NN * 384];   // x @ [Wself_sum | Wn1[0] | Wn1[1]] + bias
__device__ float g_h1 [(size_t)NN * 128];   // relu(layer-1 output)
__device__ float g_z2 [(size_t)NN * 192];   // h1 @ [Wself2_sum | Wn2[0] | Wn2[1]] + bias
__device__ float g_h2 [(size_t)NN * 64];    // layer-2 output
__device__ float g_wc1[128 * 384];
__device__ float g_bc1[384];
__device__ float g_wc2[128 * 192];
__device__ float g_bc2[192];

// ---------------- packed f32x2 helpers (Blackwell FFMA2) -------------------
__device__ __forceinline__ unsigned long long pack2(float lo, float hi) {
    unsigned long long r;
    asm("mov.b64 %0, {%1, %2};" : "=l"(r) : "f"(lo), "f"(hi));
    return r;
}
__device__ __forceinline__ void unpack2(unsigned long long v, float& lo, float& hi) {
    asm("mov.b64 {%0, %1}, %2;" : "=f"(lo), "=f"(hi) : "l"(v));
}
__device__ __forceinline__ void ffma2(unsigned long long& d,
                                      unsigned long long a, unsigned long long b) {
    asm("fma.rn.f32x2 %0, %1, %2, %0;" : "+l"(d) : "l"(a), "l"(b));
}

// ---------------- CSR build -------------------------------------------------
__global__ void zero_counts_k() {
    int i = blockIdx.x * blockDim.x + threadIdx.x;
    if (i < 2 * (NN + 1)) g_count[i] = 0;
}

__global__ void count_k(const int* __restrict__ edges) {
    int idx = blockIdx.x * blockDim.x + threadIdx.x;
    if (idx >= 2 * EE) return;
    int r = idx / EE;
    int e = idx - r * EE;
    int dst = edges[r * 2 * EE + EE + e];
    atomicAdd(&g_count[r * (NN + 1) + dst], 1);
}

__device__ __forceinline__ int warp_incl_scan(int v, int lane) {
#pragma unroll
    for (int o = 1; o < 32; o <<= 1) {
        int t = __shfl_up_sync(0xffffffffu, v, o);
        if (lane >= o) v += t;
    }
    return v;
}

__global__ void scan_k() {
    int r = blockIdx.x;
    int* cnt = g_count  + r * (NN + 1);
    int* rp  = g_rowptr + r * (NN + 1);
    __shared__ int wsum[32];
    __shared__ int s_carry;
    __shared__ int s_total;
    int tid = threadIdx.x, lane = tid & 31, wid = tid >> 5;
    if (tid == 0) s_carry = 0;
    __syncthreads();
    for (int base = 0; base < NN; base += 1024) {
        int i = base + tid;
        int v = (i < NN) ? cnt[i] : 0;
        int incl = warp_incl_scan(v, lane);
        if (lane == 31) wsum[wid] = incl;
        __syncthreads();
        if (wid == 0) {
            int w = wsum[lane];
            int wi = warp_incl_scan(w, lane);
            wsum[lane] = wi - w;
            if (lane == 31) s_total = wi;
        }
        __syncthreads();
        int excl = s_carry + wsum[wid] + incl - v;
        if (i < NN) { rp[i] = excl; cnt[i] = excl; }
        __syncthreads();
        if (tid == 0) s_carry += s_total;
        __syncthreads();
    }
    if (threadIdx.x == 0) rp[NN] = s_carry;
}

__global__ void fill_k(const int* __restrict__ edges) {
    int idx = blockIdx.x * blockDim.x + threadIdx.x;
    if (idx >= 2 * EE) return;
    int r = idx / EE;
    int e = idx - r * EE;
    int src = edges[r * 2 * EE + e];
    int dst = edges[r * 2 * EE + EE + e];
    int p = atomicAdd(&g_count[r * (NN + 1) + dst], 1);
    g_col[r * EE + p] = src;
}

// ---------------- combined weight/bias builder (one launch) -----------------
__global__ void buildW_k(const float* __restrict__ Ws1, const float* __restrict__ Wn1,
                         const float* __restrict__ b1,
                         const float* __restrict__ Ws2, const float* __restrict__ Wn2,
                         const float* __restrict__ b2) {
    int i = blockIdx.x * blockDim.x + threadIdx.x;
    if (i < 128 * 384) {
        int k = i / 384, c = i - k * 384;
        float v;
        if (c < 128) v = Ws1[k * 128 + c] + Ws1[128 * 128 + k * 128 + c];
        else {
            int r = (c - 128) >> 7, cc = (c - 128) & 127;
            v = Wn1[r * 128 * 128 + k * 128 + cc];
        }
        g_wc1[i] = v;
    } else if (i < 128 * 384 + 128 * 192) {
        int j = i - 128 * 384;
        int k = j / 192, c = j - k * 192;
        float v;
        if (c < 64) v = Ws2[k * 64 + c] + Ws2[128 * 64 + k * 64 + c];
        else {
            int r = (c - 64) >> 6, cc = (c - 64) & 63;
            v = Wn2[r * 128 * 64 + k * 64 + cc];
        }
        g_wc2[j] = v;
    } else if (i < 128 * 384 + 128 * 192 + 384) {
        int c = i - (128 * 384 + 128 * 192);
        g_bc1[c] = (c < 128) ? b1[c] + b1[128 + c] : 0.f;
    } else if (i < 128 * 384 + 128 * 192 + 384 + 192) {
        int c = i - (128 * 384 + 128 * 192 + 384);
        g_bc2[c] = (c < 64) ? b2[c] + b2[64 + c] : 0.f;
    }
}

// ---------------- SGEMM with packed FFMA2 -----------------------------------
// C[N x FOUT] = A[N x 128] @ W[128 x FOUT] + bias   (col-tiled by COLT)
template <int FOUT, int COLT>
__global__ void __launch_bounds__(256) gemm2_k(const float* __restrict__ A,
                                               const float* __restrict__ W,
                                               const float* __restrict__ bias,
                                               float* __restrict__ C) {
    constexpr int TN = COLT / 16;   // 8 (COLT=128) or 6 (COLT=96)
    constexpr int KC = 32;
    __shared__ unsigned long long As2[KC][128];  // duplicated pairs (32 KB)
    __shared__ float Ws[KC][COLT];

    const int tid = threadIdx.x;
    const int ty = tid >> 4, tx = tid & 15;
    const int rowBlock = blockIdx.x * 128;
    const int colBlock = blockIdx.y * COLT;

    unsigned long long acc[8][TN / 2];
#pragma unroll
    for (int i = 0; i < 8; i++)
#pragma unroll
        for (int j = 0; j < TN / 2; j++) acc[i][j] = 0ull;

    for (int kb = 0; kb < 128; kb += KC) {
#pragma unroll
        for (int it = 0; it < 4; it++) {
            int idx = tid + it * 256;      // 0..1023
            int row = idx >> 3;            // 0..127
            int kq  = idx & 7;             // k-quad 0..7
            float4 v = make_float4(0.f, 0.f, 0.f, 0.f);
            int grow = rowBlock + row;
            if (grow < NN)
                v = *(const float4*)(A + (size_t)grow * 128 + kb + kq * 4);
            As2[kq * 4 + 0][row] = pack2(v.x, v.x);
            As2[kq * 4 + 1][row] = pack2(v.y, v.y);
            As2[kq * 4 + 2][row] = pack2(v.z, v.z);
            As2[kq * 4 + 3][row] = pack2(v.w, v.w);
        }
#pragma unroll
        for (int idx = tid; idx < KC * COLT / 4; idx += 256) {
            int k  = idx / (COLT / 4);
            int c4 = idx - k * (COLT / 4);
            *(float4*)&Ws[k][c4 * 4] =
                *(const float4*)(W + (size_t)(kb + k) * FOUT + colBlock + c4 * 4);
        }
        __syncthreads();

#pragma unroll
        for (int k = 0; k < KC; k++) {
            unsigned long long a2[8];
            const ulonglong2* ap = (const ulonglong2*)&As2[k][ty * 8];
#pragma unroll
            for (int i = 0; i < 4; i++) {
                ulonglong2 t = ap[i];
                a2[2 * i] = t.x; a2[2 * i + 1] = t.y;
            }
            unsigned long long b2[TN / 2];
            if (TN == 8) {
                const ulonglong2* wp = (const ulonglong2*)&Ws[k][tx * TN];
#pragma unroll
                for (int j = 0; j < 2; j++) {
                    ulonglong2 t = wp[j];
                    b2[2 * j] = t.x; b2[2 * j + 1] = t.y;
                }
            } else {
                const unsigned long long* wp =
                    (const unsigned long long*)&Ws[k][tx * TN];
#pragma unroll
                for (int j = 0; j < TN / 2; j++) b2[j] = wp[j];
            }
#pragma unroll
            for (int i = 0; i < 8; i++)
#pragma unroll
                for (int j = 0; j < TN / 2; j++)
                    ffma2(acc[i][j], a2[i], b2[j]);
        }
        __syncthreads();
    }

#pragma unroll
    for (int i = 0; i < 8; i++) {
        int grow = rowBlock + ty * 8 + i;
        if (grow < NN) {
            float* cr = C + (size_t)grow * FOUT + colBlock + tx * TN;
            const float* bp = bias + colBlock + tx * TN;
#pragma unroll
            for (int j = 0; j < TN / 2; j++) {
                float lo, hi;
                unpack2(acc[i][j], lo, hi);
                float2 o = make_float2(lo + bp[2 * j], hi + bp[2 * j + 1]);
                *(float2*)(cr + 2 * j) = o;
            }
        }
    }
}

// ---------------- fused aggregation epilogues (unroll-4 for MLP) ------------
// layer 1: h1[n] = relu( Z1[n,0:128] + sum_r mean_{src in N_r(n)} Z1[src,128+128r:256+128r] )
__global__ void agg1_k() {
    int gw   = (blockIdx.x * blockDim.x + threadIdx.x) >> 5;
    int lane = threadIdx.x & 31;
    if (gw >= NN) return;
    float4 acc = ((const float4*)(g_z1 + (size_t)gw * 384))[lane];
#pragma unroll
    for (int r = 0; r < 2; r++) {
        const int* rp  = g_rowptr + r * (NN + 1);
        const int* col = g_col    + r * EE;
        int s = rp[gw], e = rp[gw + 1];
        const float4* base = (const float4*)(g_z1 + 128 + r * 128) + lane;
        float4 sum = make_float4(0.f, 0.f, 0.f, 0.f);
        int j = s;
        for (; j + 3 < e; j += 4) {
            int s0 = col[j], s1 = col[j + 1], s2 = col[j + 2], s3 = col[j + 3];
            float4 v0 = __ldg(base + (size_t)s0 * 96);
            float4 v1 = __ldg(base + (size_t)s1 * 96);
            float4 v2 = __ldg(base + (size_t)s2 * 96);
            float4 v3 = __ldg(base + (size_t)s3 * 96);
            sum.x += v0.x + v1.x + v2.x + v3.x;
            sum.y += v0.y + v1.y + v2.y + v3.y;
            sum.z += v0.z + v1.z + v2.z + v3.z;
            sum.w += v0.w + v1.w + v2.w + v3.w;
        }
        for (; j < e; j++) {
            float4 v = __ldg(base + (size_t)col[j] * 96);
            sum.x += v.x; sum.y += v.y; sum.z += v.z; sum.w += v.w;
        }
        float inv = (e > s) ? 1.0f / (float)(e - s) : 0.0f;
        acc.x += sum.x * inv; acc.y += sum.y * inv;
        acc.z += sum.z * inv; acc.w += sum.w * inv;
    }
    acc.x = fmaxf(acc.x, 0.f); acc.y = fmaxf(acc.y, 0.f);
    acc.z = fmaxf(acc.z, 0.f); acc.w = fmaxf(acc.w, 0.f);
    ((float4*)(g_h1 + (size_t)gw * 128))[lane] = acc;
}

// layer 2: h2[n] = Z2[n,0:64] + sum_r mean_{src in N_r(n)} Z2[src,64+64r:128+64r]
__global__ void agg2_k() {
    int gw   = (blockIdx.x * blockDim.x + threadIdx.x) >> 5;
    int lane = threadIdx.x & 31;
    if (gw >= NN) return;
    float2 acc = ((const float2*)(g_z2 + (size_t)gw * 192))[lane];
#pragma unroll
    for (int r = 0; r < 2; r++) {
        const int* rp  = g_rowptr + r * (NN + 1);
        const int* col = g_col    + r * EE;
        int s = rp[gw], e = rp[gw + 1];
        const float2* base = (const float2*)(g_z2 + 64 + r * 64) + lane;
        float2 sum = make_float2(0.f, 0.f);
        int j = s;
        for (; j + 3 < e; j += 4) {
            int s0 = col[j], s1 = col[j + 1], s2 = col[j + 2], s3 = col[j + 3];
            float2 v0 = __ldg(base + (size_t)s0 * 96);
            float2 v1 = __ldg(base + (size_t)s1 * 96);
            float2 v2 = __ldg(base + (size_t)s2 * 96);
            float2 v3 = __ldg(base + (size_t)s3 * 96);
            sum.x += v0.x + v1.x + v2.x + v3.x;
            sum.y += v0.y + v1.y + v2.y + v3.y;
        }
        for (; j < e; j++) {
            float2 v = __ldg(base + (size_t)col[j] * 96);
            sum.x += v.x; sum.y += v.y;
        }
        float inv = (e > s) ? 1.0f / (float)(e - s) : 0.0f;
        acc.x += sum.x * inv; acc.y += sum.y * inv;
    }
    ((float2*)(g_h2 + (size_t)gw * 64))[lane] = acc;
}

// ---------------- scoring: dot(h2[u], h2[v]) over pos + neg edges -----------
__global__ void score_k(const int* __restrict__ edges, const int* __restrict__ neg,
                        float* __restrict__ out) {
    int gid  = blockIdx.x * blockDim.x + threadIdx.x;
    int eidx = gid >> 3;
    int sub  = gid & 7;
    if (eidx >= 2 * EE) return;
    int u, v;
    if (eidx < EE) { u = edges[eidx];           v = edges[EE + eidx]; }
    else           { int e = eidx - EE; u = neg[e]; v = neg[EE + e]; }
    const float4* hu = (const float4*)(g_h2 + (size_t)u * 64);
    const float4* hv = (const float4*)(g_h2 + (size_t)v * 64);
    float4 a0 = hu[sub * 2], a1 = hu[sub * 2 + 1];
    float4 b0 = hv[sub * 2], b1 = hv[sub * 2 + 1];
    float s = a0.x * b0.x + a0.y * b0.y + a0.z * b0.z + a0.w * b0.w
            + a1.x * b1.x + a1.y * b1.y + a1.z * b1.z + a1.w * b1.w;
    s += __shfl_xor_sync(0xffffffffu, s, 1);
    s += __shfl_xor_sync(0xffffffffu, s, 2);
    s += __shfl_xor_sync(0xffffffffu, s, 4);
    if (sub == 0) out[eidx] = s;
}

// ---------------- launch -----------------------------------------------------
extern "C" void kernel_launch(void* const* d_in, const int* in_sizes, int n_in,
                              void* d_out, int out_size) {
    const float* x     = (const float*)d_in[0];
    const int*   edges = (const int*)  d_in[1];
    const int*   nege  = (const int*)  d_in[2];
    const float* Wn1   = (const float*)d_in[3];   // [2,128,128]
    const float* Ws1   = (const float*)d_in[4];
    const float* b1    = (const float*)d_in[5];
    const float* Wn2   = (const float*)d_in[6];   // [2,128,64]
    const float* Ws2   = (const float*)d_in[7];
    const float* b2    = (const float*)d_in[8];
    float* out = (float*)d_out;

    void *pz1_, *ph1_, *pz2_, *pwc1_, *pbc1_, *pwc2_, *pbc2_;
    cudaGetSymbolAddress(&pz1_,  g_z1);
    cudaGetSymbolAddress(&ph1_,  g_h1);
    cudaGetSymbolAddress(&pz2_,  g_z2);
    cudaGetSymbolAddress(&pwc1_, g_wc1);
    cudaGetSymbolAddress(&pbc1_, g_bc1);
    cudaGetSymbolAddress(&pwc2_, g_wc2);
    cudaGetSymbolAddress(&pbc2_, g_bc2);
    float* pz1  = (float*)pz1_;
    float* ph1  = (float*)ph1_;
    float* pz2  = (float*)pz2_;
    float* pwc1 = (float*)pwc1_;
    float* pbc1 = (float*)pbc1_;
    float* pwc2 = (float*)pwc2_;
    float* pbc2 = (float*)pbc2_;

    // Side stream + events: CSR build (atomic/L2-bound, issue~5%) overlaps
    // GEMM1 (fma-bound). Created on the pre-capture correctness call; during
    // capture they are fork/join dependency edges (capture-legal).
    static cudaStream_t sB = nullptr;
    static cudaEvent_t evFork = nullptr, evCSR = nullptr;
    if (!sB) {
        cudaStreamCreateWithFlags(&sB, cudaStreamNonBlocking);
        cudaEventCreateWithFlags(&evFork, cudaEventDisableTiming);
        cudaEventCreateWithFlags(&evCSR,  cudaEventDisableTiming);
    }

    const int edgeBlocks     = (2 * EE + 255) / 256;       // 6250
    const int nodeWarpBlocks = (NN * 32 + 255) / 256;      // 6250
    const int gemmRowBlocks  = (NN + 127) / 128;           // 391

    // ---- fork: CSR build on side stream (independent of GEMM1) ----
    cudaEventRecord(evFork, 0);
    cudaStreamWaitEvent(sB, evFork, 0);
    zero_counts_k<<<(2 * (NN + 1) + 255) / 256, 256, 0, sB>>>();
    count_k<<<edgeBlocks, 256, 0, sB>>>(edges);
    scan_k<<<2, 1024, 0, sB>>>();
    fill_k<<<edgeBlocks, 256, 0, sB>>>(edges);
    cudaEventRecord(evCSR, sB);

    // ---- main stream: combined weights (one launch), then GEMM1 ----
    buildW_k<<<(128 * 384 + 128 * 192 + 384 + 192 + 255) / 256, 256>>>(
        Ws1, Wn1, b1, Ws2, Wn2, b2);
    gemm2_k<384, 128><<<dim3(gemmRowBlocks, 3), 256>>>(x, pwc1, pbc1, pz1);

    // ---- join: agg1 needs the CSR ----
    cudaStreamWaitEvent(0, evCSR, 0);
    agg1_k<<<nodeWarpBlocks, 256>>>();

    // ---- layer 2 (unchunked: 782 blocks = 5.3 waves, no quantization) ----
    gemm2_k<192, 96><<<dim3(gemmRowBlocks, 2), 256>>>(ph1, pwc2, pbc2, pz2);
    agg2_k<<<nodeWarpBlocks, 256>>>();

    // ---- scoring: out[0:E]=pos, out[E:2E]=neg ----
    score_k<<<(2 * EE * 8 + 255) / 256, 256>>>(edges, nege, out);
}